// round 12
// baseline (speedup 1.0000x reference)
#include <cuda_runtime.h>
#include <cuda_bf16.h>
#include <cuda_fp16.h>
#include <cstdint>
#include <math.h>

// ---------------------------------------------------------------------------
// SNN 5-layer LIF, 25 steps, batch 2048, dims 100->128->256->512->1024->784.
// Persistent dataflow kernel with PER-M-SLICE dependency counters:
// D[stage][t][m] (m = 128-row batch slice). Items popped in topological
// (diagonal, LPT) order from an atomic queue; each item waits only on its own
// m-slice deps => cross-diagonal overlap, no global drains, no wave
// quantization. GEMMs: HMMA fp16, 2-way split w/ scaled lo (hi=fp16(w),
// lo=fp16(4096*(w-hi)), residual ~w*2^-24), dual accumulation chains,
// BK=64 superstages, ping-pong smem ring. Layer-1 current computed once.
// ---------------------------------------------------------------------------

#define BETA_ 0.95f
#define LO_SCALE 4096.0f
#define LO_INV 2.44140625e-4f  // 2^-12, exact

namespace {
constexpr int BATCH = 2048;
constexpr int TSTEPS = 25;
constexpr int WSZ2 = 256 * 128, WSZ3 = 512 * 256, WSZ4 = 1024 * 512;
constexpr int WSZ5 = 784 * 1024;   // real
constexpr int WSZ5P = 832 * 1024;  // padded N to multiple of 64
constexpr size_t WOFF2 = 0;
constexpr size_t WOFF3 = WOFF2 + 2ull * WSZ2;
constexpr size_t WOFF4 = WOFF3 + 2ull * WSZ3;
constexpr size_t WOFF5 = WOFF4 + 2ull * WSZ4;
constexpr size_t WTOT = WOFF5 + 2ull * WSZ5P;
constexpr size_t SPK_STRIDE = (size_t)BATCH * (128 + 256 + 512 + 1024);
// per-diagonal block ranges (longest first -> LPT within queue order)
constexpr int NB_L5 = 13 * 16;   // 208  K=1024
constexpr int NB_L4 = 16 * 16;   // 256  K=512
constexpr int NB_L3 = 8 * 16;    // 128  K=256
constexpr int NB_L2 = 4 * 16;    // 64   K=128
constexpr int NB_LIF = 16;       // one per m-slice
constexpr int NB_TOT = NB_L5 + NB_L4 + NB_L3 + NB_L2 + NB_LIF;  // 672
constexpr int NDIAG = TSTEPS + 4;                               // 29
constexpr int NITEMS = NDIAG * NB_TOT;
constexpr int SUB_B = 8192 + 2 * 4096;   // 32-K sub-tile: A 8K + 2 B splits
constexpr int STAGE_B = 2 * SUB_B;       // 64-K superstage = 32KB
constexpr int SMEM_DYN = 2 * STAGE_B;    // ping-pong ring = 64KB
constexpr int NWORKERS = 296;
// stages
constexpr int ST_LIF = 0, ST_L2 = 1, ST_L3 = 2, ST_L4 = 3, ST_L5 = 4;
// expected done-count per (stage, t, m) = number of n-tiles
__device__ __constant__ int NT_CNT[5] = {1, 4, 8, 16, 13};
constexpr int SYNC_INTS = 8 + 5 * 32 * 16;  // qhead + D[5][32][16]
}  // namespace

// ---- persistent scratch (__device__ globals; no allocs allowed) ----
__device__ __align__(16) float g_mem[(size_t)BATCH * (128 + 256 + 512 + 1024 + 784)];
__device__ __align__(16) __half g_spkb[2 * SPK_STRIDE];  // parity double buffer
__device__ __align__(16) float g_cur1[(size_t)BATCH * 128];
__device__ __align__(16) __half g_wsplit[WTOT];  // zero-init: L5 pad rows stay 0
__device__ int g_sync[SYNC_INTS];  // [0]=queue head; D at offset 8

__device__ __forceinline__ int* done_ctr(int stage, int t, int m) {
    return &g_sync[8 + (stage * 32 + t) * 16 + m];
}

// ======================= PTX helpers (arch-neutral) ========================
__device__ __forceinline__ uint32_t smem_u32(const void* p) {
    uint32_t a;
    asm("{ .reg .u64 t; cvta.to.shared.u64 t, %1; cvt.u32.u64 %0, t; }" : "=r"(a) : "l"(p));
    return a;
}
__device__ __forceinline__ void cp_async16(uint32_t dst, const void* src) {
    asm volatile("cp.async.cg.shared.global [%0], [%1], 16;" ::"r"(dst), "l"(src));
}
#define CP_COMMIT() asm volatile("cp.async.commit_group;" ::: "memory")
#define CP_WAIT0() asm volatile("cp.async.wait_group 0;" ::: "memory")

__device__ __forceinline__ void ldsm_x4(uint32_t& r0, uint32_t& r1, uint32_t& r2, uint32_t& r3,
                                        uint32_t addr) {
    asm volatile("ldmatrix.sync.aligned.m8n8.x4.shared.b16 {%0,%1,%2,%3}, [%4];"
                 : "=r"(r0), "=r"(r1), "=r"(r2), "=r"(r3)
                 : "r"(addr));
}
__device__ __forceinline__ void mma_f16(float* c, const uint32_t* a, const uint32_t* b) {
    asm volatile(
        "mma.sync.aligned.m16n8k16.row.col.f32.f16.f16.f32 "
        "{%0,%1,%2,%3}, {%4,%5,%6,%7}, {%8,%9}, {%0,%1,%2,%3};"
        : "+f"(c[0]), "+f"(c[1]), "+f"(c[2]), "+f"(c[3])
        : "r"(a[0]), "r"(a[1]), "r"(a[2]), "r"(a[3]), "r"(b[0]), "r"(b[1]));
}
__device__ __forceinline__ void mma_f16_z(float* d, const uint32_t* a, const uint32_t* b,
                                          const float* z) {
    asm volatile(
        "mma.sync.aligned.m16n8k16.row.col.f32.f16.f16.f32 "
        "{%0,%1,%2,%3}, {%4,%5,%6,%7}, {%8,%9}, {%10,%11,%12,%13};"
        : "=f"(d[0]), "=f"(d[1]), "=f"(d[2]), "=f"(d[3])
        : "r"(a[0]), "r"(a[1]), "r"(a[2]), "r"(a[3]), "r"(b[0]), "r"(b[1]),
          "f"(z[0]), "f"(z[1]), "f"(z[2]), "f"(z[3]));
}

// ======================= setup kernels =====================================
__global__ void zero_kernel(float* __restrict__ p, int n) {
    int i = blockIdx.x * blockDim.x + threadIdx.x;
    for (; i < n; i += gridDim.x * blockDim.x) p[i] = 0.0f;
}
__global__ void zero_sync_kernel() {
    for (int i = threadIdx.x; i < SYNC_INTS; i += blockDim.x) g_sync[i] = 0;
}

// 2-way fp16 split, lo scaled by 2^12 into the normal fp16 range
__global__ void split_kernel(const float* __restrict__ W2, const float* __restrict__ W3,
                             const float* __restrict__ W4, const float* __restrict__ W5) {
    const int total = WSZ2 + WSZ3 + WSZ4 + WSZ5;
    for (int i = blockIdx.x * blockDim.x + threadIdx.x; i < total;
         i += gridDim.x * blockDim.x) {
        const float* src;
        size_t base;
        int local, stride;
        if (i < WSZ2) { src = W2; base = WOFF2; local = i; stride = WSZ2; }
        else if (i < WSZ2 + WSZ3) { src = W3; base = WOFF3; local = i - WSZ2; stride = WSZ3; }
        else if (i < WSZ2 + WSZ3 + WSZ4) { src = W4; base = WOFF4; local = i - WSZ2 - WSZ3; stride = WSZ4; }
        else { src = W5; base = WOFF5; local = i - WSZ2 - WSZ3 - WSZ4; stride = WSZ5P; }
        float w = src[local];
        __half hi = __float2half_rn(w);
        float r1 = w - __half2float(hi);
        __half lo = __float2half_rn(r1 * LO_SCALE);
        g_wsplit[base + local] = hi;
        g_wsplit[base + (size_t)stride + local] = lo;
    }
}

// ---- fp32 SIMT GEMM for layer 1 (runs once): C = relu(A@W^T + b) ----
namespace {
constexpr int L1BM = 128, L1BN = 64, L1BK = 16;
constexpr int LDA_S = L1BM + 4, LDB_S = L1BN + 4;
}
__global__ __launch_bounds__(256, 2) void gemm_l1(const float* __restrict__ A,
                                                  const float* __restrict__ W,
                                                  const float* __restrict__ bias,
                                                  float* __restrict__ outc, int N, int K) {
    __shared__ float As[L1BK * LDA_S];
    __shared__ float Bs[L1BK * LDB_S];
    const int tid = threadIdx.x;
    const int tx = tid & 15, ty = tid >> 4;
    const int bn0 = blockIdx.x * L1BN, bm0 = blockIdx.y * L1BM;
    float acc[8][4];
#pragma unroll
    for (int i = 0; i < 8; i++)
#pragma unroll
        for (int j = 0; j < 4; j++) acc[i][j] = 0.0f;
    const int ktiles = (K + L1BK - 1) / L1BK;
    for (int kt = 0; kt < ktiles; kt++) {
        const int k0 = kt * L1BK;
#pragma unroll
        for (int r = 0; r < 2; r++) {
            int f = tid + r * 256;
            int m = f >> 2, kq = f & 3, k = k0 + kq * 4;
            float4 v = make_float4(0.f, 0.f, 0.f, 0.f);
            if (k < K) v = *reinterpret_cast<const float4*>(A + (size_t)(bm0 + m) * K + k);
            As[(kq * 4 + 0) * LDA_S + m] = v.x;
            As[(kq * 4 + 1) * LDA_S + m] = v.y;
            As[(kq * 4 + 2) * LDA_S + m] = v.z;
            As[(kq * 4 + 3) * LDA_S + m] = v.w;
        }
        {
            int n = tid >> 2, kq = tid & 3, k = k0 + kq * 4, gn = bn0 + n;
            float4 v = make_float4(0.f, 0.f, 0.f, 0.f);
            if (k < K && gn < N) v = *reinterpret_cast<const float4*>(W + (size_t)gn * K + k);
            Bs[(kq * 4 + 0) * LDB_S + n] = v.x;
            Bs[(kq * 4 + 1) * LDB_S + n] = v.y;
            Bs[(kq * 4 + 2) * LDB_S + n] = v.z;
            Bs[(kq * 4 + 3) * LDB_S + n] = v.w;
        }
        __syncthreads();
#pragma unroll
        for (int k = 0; k < L1BK; k++) {
            float a[8], bb[4];
            *reinterpret_cast<float4*>(a) = *reinterpret_cast<const float4*>(&As[k * LDA_S + ty * 8]);
            *reinterpret_cast<float4*>(a + 4) =
                *reinterpret_cast<const float4*>(&As[k * LDA_S + ty * 8 + 4]);
            *reinterpret_cast<float4*>(bb) = *reinterpret_cast<const float4*>(&Bs[k * LDB_S + tx * 4]);
#pragma unroll
            for (int i = 0; i < 8; i++)
#pragma unroll
                for (int j = 0; j < 4; j++) acc[i][j] = fmaf(a[i], bb[j], acc[i][j]);
        }
        __syncthreads();
    }
#pragma unroll
    for (int j = 0; j < 4; j++) {
        int gn = bn0 + tx * 4 + j;
        if (gn >= N) continue;
        float bv = bias[gn];
#pragma unroll
        for (int i = 0; i < 8; i++) {
            int gm = bm0 + ty * 8 + i;
            outc[(size_t)gm * N + gn] = fmaxf(acc[i][j] + bv, 0.0f);
        }
    }
}

// ================= per-block fused HMMA GEMM + LIF =========================
// CTA tile 128x64; BK=64 superstage (two 32-K sub-tiles); ping-pong ring.
// Dual chains per sub-tile; flush accm += tmpH; accm = fma(2^-12, tmpL, .).
template <int N_REAL, int N_PAD, int K, int LAST>
__device__ __forceinline__ void gemm_block(
    int bn_t, int bm_t, const __half* __restrict__ A,
    const __half* __restrict__ Wsp, const float* __restrict__ bias,
    float* __restrict__ mem, __half* __restrict__ spk_h,
    float* __restrict__ out_spk, float* __restrict__ out_mem) {
    extern __shared__ __align__(128) char smem[];
    constexpr int KT = K / 64;
    constexpr int A_BYTES = 8192, B_BYTES = 4096;

    const int tid = threadIdx.x;
    const int wid = tid >> 5, lane = tid & 31;
    const int wM = wid >> 2, wN = wid & 3;
    const int bn0 = bn_t * 64, bm0 = bm_t * 128;
    const size_t WSZ = (size_t)N_PAD * K;
    const uint32_t sb = smem_u32(smem);

    const float zf[4] = {0.0f, 0.0f, 0.0f, 0.0f};

    auto issue = [&](int kt) {
        const uint32_t st = sb + (kt & 1) * STAGE_B;
#pragma unroll
        for (int sub = 0; sub < 2; sub++) {
            const int k0 = kt * 64 + sub * 32;
            const uint32_t sd = st + sub * SUB_B;
#pragma unroll
            for (int i = 0; i < 2; i++) {
                int f = tid + i * 256;
                int row = f >> 2, c = f & 3;
                cp_async16(sd + row * 64 + ((c ^ ((row >> 1) & 3)) * 16),
                           A + (size_t)(bm0 + row) * K + k0 + c * 8);
            }
#pragma unroll
            for (int s = 0; s < 2; s++) {
                int row = tid >> 2, c = tid & 3;
                cp_async16(sd + A_BYTES + s * B_BYTES + row * 64 +
                               ((c ^ ((row >> 1) & 3)) * 16),
                           Wsp + (size_t)s * WSZ + (size_t)(bn0 + row) * K + k0 + c * 8);
            }
        }
    };

    float accm[4][2][4];
#pragma unroll
    for (int i = 0; i < 4; i++)
#pragma unroll
        for (int j = 0; j < 2; j++)
#pragma unroll
            for (int q = 0; q < 4; q++) accm[i][j][q] = 0.0f;

    issue(0);
    CP_COMMIT();
    for (int kt = 0; kt < KT; kt++) {
        CP_WAIT0();
        __syncthreads();
        if (kt + 1 < KT) issue(kt + 1);
        CP_COMMIT();
#pragma unroll
        for (int sub = 0; sub < 2; sub++) {
            const uint32_t sA = sb + (kt & 1) * STAGE_B + sub * SUB_B;
            const uint32_t sB = sA + A_BYTES;

            float tmpH[4][2][4], tmpL[4][2][4];
#pragma unroll
            for (int k16 = 0; k16 < 2; k16++) {
                uint32_t afr[4][4];
#pragma unroll
                for (int mf = 0; mf < 4; mf++) {
                    int row = wM * 64 + mf * 16 + (lane & 15);
                    int chunk = k16 * 2 + ((lane >> 4) & 1);
                    uint32_t addr = sA + row * 64 + ((chunk ^ ((row >> 1) & 3)) * 16);
                    ldsm_x4(afr[mf][0], afr[mf][1], afr[mf][2], afr[mf][3], addr);
                }
#pragma unroll
                for (int s = 0; s < 2; s++) {
                    uint32_t bfr[4];
                    {
                        int row = wN * 16 + (lane & 7) + ((lane >> 4) & 1) * 8;
                        int chunk = k16 * 2 + ((lane >> 3) & 1);
                        uint32_t addr =
                            sB + s * B_BYTES + row * 64 + ((chunk ^ ((row >> 1) & 3)) * 16);
                        ldsm_x4(bfr[0], bfr[1], bfr[2], bfr[3], addr);
                    }
                    float (*tmp)[2][4] = (s == 0) ? tmpH : tmpL;
#pragma unroll
                    for (int mf = 0; mf < 4; mf++) {
                        if (k16 == 0) {
                            mma_f16_z(tmp[mf][0], afr[mf], bfr, zf);
                            mma_f16_z(tmp[mf][1], afr[mf], bfr + 2, zf);
                        } else {
                            mma_f16(tmp[mf][0], afr[mf], bfr);
                            mma_f16(tmp[mf][1], afr[mf], bfr + 2);
                        }
                    }
                }
            }
#pragma unroll
            for (int i = 0; i < 4; i++)
#pragma unroll
                for (int j = 0; j < 2; j++)
#pragma unroll
                    for (int q = 0; q < 4; q++) {
                        float a = accm[i][j][q] + tmpH[i][j][q];
                        accm[i][j][q] = fmaf(LO_INV, tmpL[i][j][q], a);
                    }
        }
    }

    // ---- epilogue: bias + relu + LIF (+ outputs) ----
    const int tg = lane >> 2;
    const int tc = (lane & 3) * 2;
#pragma unroll
    for (int mf = 0; mf < 4; mf++) {
#pragma unroll
        for (int nf = 0; nf < 2; nf++) {
            int gn0 = bn0 + wN * 16 + nf * 8 + tc;
            int r0 = bm0 + wM * 64 + mf * 16 + tg;
#pragma unroll
            for (int h = 0; h < 2; h++) {
                int r = r0 + h * 8;
#pragma unroll
                for (int q = 0; q < 2; q++) {
                    int n = gn0 + q;
                    if (N_REAL == N_PAD || n < N_REAL) {
                        float v = accm[mf][nf][h * 2 + q];
                        float cur = fmaxf(v + bias[n], 0.0f);
                        size_t idx = (size_t)r * N_REAL + n;
                        float mo = mem[idx];
                        float reset = (mo > 1.0f) ? 1.0f : 0.0f;
                        float mn = fmaf(BETA_, mo, cur) - reset;
                        mem[idx] = mn;
                        float s = (mn > 1.0f) ? 1.0f : 0.0f;
                        if (LAST) {
                            out_spk[idx] = s;
                            out_mem[idx] = tanhf(mn);
                        } else {
                            spk_h[idx] = __float2half_rn(s);
                        }
                    }
                }
            }
        }
    }
}

// ================== persistent fine-grained dataflow kernel =================
__device__ __forceinline__ void dep_wait(int stage, int t, int m) {
    volatile int* p = (volatile int*)done_ctr(stage, t, m);
    const int tgt = NT_CNT[stage];
    while (*p < tgt) __nanosleep(64);
}

__global__ __launch_bounds__(256, 2) void snn_persistent(
    const float* __restrict__ b2, const float* __restrict__ b3,
    const float* __restrict__ b4, const float* __restrict__ b5,
    float* __restrict__ out) {
    __shared__ int s_g;
    float* mem1 = g_mem;
    float* mem2 = g_mem + (size_t)BATCH * 128;
    float* mem3 = g_mem + (size_t)BATCH * (128 + 256);
    float* mem4 = g_mem + (size_t)BATCH * (128 + 256 + 512);
    float* mem5 = g_mem + (size_t)BATCH * (128 + 256 + 512 + 1024);

    for (;;) {
        if (threadIdx.x == 0) s_g = atomicAdd(&g_sync[0], 1);
        __syncthreads();
        const int g = s_g;
        if (g >= NITEMS) return;
        const int d = g / NB_TOT;
        const int b = g - d * NB_TOT;

        int stage, t, nn, mm;
        if (b < NB_L5) { stage = ST_L5; t = d - 4; nn = b % 13; mm = b / 13; }
        else if (b < NB_L5 + NB_L4) {
            int i = b - NB_L5; stage = ST_L4; t = d - 3; nn = i & 15; mm = i >> 4;
        } else if (b < NB_L5 + NB_L4 + NB_L3) {
            int i = b - NB_L5 - NB_L4; stage = ST_L3; t = d - 2; nn = i & 7; mm = i >> 3;
        } else if (b < NB_L5 + NB_L4 + NB_L3 + NB_L2) {
            int i = b - NB_L5 - NB_L4 - NB_L3; stage = ST_L2; t = d - 1; nn = i & 3; mm = i >> 2;
        } else {
            stage = ST_LIF; t = d; nn = 0; mm = b - (NB_L5 + NB_L4 + NB_L3 + NB_L2);
        }
        if (t < 0 || t >= TSTEPS) continue;  // uniform across block

        // ---- per-m-slice dependency wait (tid 0 spins) ----
        if (threadIdx.x == 0) {
            switch (stage) {
                case ST_LIF:
                    if (t > 0) dep_wait(ST_LIF, t - 1, mm);
                    if (t >= 2) dep_wait(ST_L2, t - 2, mm);   // spk1 parity anti-dep
                    break;
                case ST_L2:
                    dep_wait(ST_LIF, t, mm);
                    if (t > 0) dep_wait(ST_L2, t - 1, mm);
                    if (t >= 2) dep_wait(ST_L3, t - 2, mm);   // spk2 parity anti-dep
                    break;
                case ST_L3:
                    dep_wait(ST_L2, t, mm);
                    if (t > 0) dep_wait(ST_L3, t - 1, mm);
                    if (t >= 2) dep_wait(ST_L4, t - 2, mm);   // spk3 parity anti-dep
                    break;
                case ST_L4:
                    dep_wait(ST_L3, t, mm);
                    if (t > 0) dep_wait(ST_L4, t - 1, mm);
                    if (t >= 2) dep_wait(ST_L5, t - 2, mm);   // spk4 parity anti-dep
                    break;
                default:  // ST_L5
                    dep_wait(ST_L4, t, mm);
                    if (t > 0) dep_wait(ST_L5, t - 1, mm);
                    break;
            }
            __threadfence();
        }
        __syncthreads();

        // ---- execute ----
        const int p = t & 1;
        const size_t pb = (size_t)p * SPK_STRIDE;
        if (stage == ST_L5) {
            const __half* spk4 = g_spkb + pb + (size_t)BATCH * (128 + 256 + 512);
            float* o_spk = out + (size_t)t * BATCH * 784;
            float* o_mem = out + (size_t)TSTEPS * BATCH * 784 + (size_t)t * BATCH * 784;
            gemm_block<784, 832, 1024, 1>(nn, mm, spk4, g_wsplit + WOFF5, b5,
                                          mem5, nullptr, o_spk, o_mem);
        } else if (stage == ST_L4) {
            const __half* spk3 = g_spkb + pb + (size_t)BATCH * (128 + 256);
            __half* spk4 = g_spkb + pb + (size_t)BATCH * (128 + 256 + 512);
            gemm_block<1024, 1024, 512, 0>(nn, mm, spk3, g_wsplit + WOFF4, b4,
                                           mem4, spk4, nullptr, nullptr);
        } else if (stage == ST_L3) {
            const __half* spk2 = g_spkb + pb + (size_t)BATCH * 128;
            __half* spk3 = g_spkb + pb + (size_t)BATCH * (128 + 256);
            gemm_block<512, 512, 256, 0>(nn, mm, spk2, g_wsplit + WOFF3, b3,
                                         mem3, spk3, nullptr, nullptr);
        } else if (stage == ST_L2) {
            const __half* spk1 = g_spkb + pb;
            __half* spk2 = g_spkb + pb + (size_t)BATCH * 128;
            gemm_block<256, 256, 128, 0>(nn, mm, spk1, g_wsplit + WOFF2, b2,
                                         mem2, spk2, nullptr, nullptr);
        } else {  // ST_LIF: m-slice = batch rows mm*128..mm*128+127, 128 cols
            __half* spk1 = g_spkb + pb;
            const int base = mm * 128 * 128;  // contiguous range of 16384 elems
#pragma unroll 4
            for (int i = threadIdx.x; i < 128 * 128; i += 256) {
                int gi = base + i;
                float mo = mem1[gi];
                float reset = (mo > 1.0f) ? 1.0f : 0.0f;
                float mn = fmaf(BETA_, mo, g_cur1[gi]) - reset;
                mem1[gi] = mn;
                spk1[gi] = __float2half_rn((mn > 1.0f) ? 1.0f : 0.0f);
            }
        }

        // ---- publish ----
        __syncthreads();
        if (threadIdx.x == 0) {
            __threadfence();
            atomicAdd(done_ctr(stage, t, mm), 1);
        }
    }
}

// ============================= launch ======================================
extern "C" void kernel_launch(void* const* d_in, const int* in_sizes, int n_in,
                              void* d_out, int out_size) {
    const float* x = (const float*)d_in[0];
    const float* W1 = (const float*)d_in[1];
    const float* b1 = (const float*)d_in[2];
    const float* W2 = (const float*)d_in[3];
    const float* b2 = (const float*)d_in[4];
    const float* W3 = (const float*)d_in[5];
    const float* b3 = (const float*)d_in[6];
    const float* W4 = (const float*)d_in[7];
    const float* b4 = (const float*)d_in[8];
    const float* W5 = (const float*)d_in[9];
    const float* b5 = (const float*)d_in[10];
    float* out = (float*)d_out;

    float *mem_base = nullptr, *cur1 = nullptr;
    cudaGetSymbolAddress((void**)&mem_base, g_mem);
    cudaGetSymbolAddress((void**)&cur1, g_cur1);

    cudaFuncSetAttribute(snn_persistent, cudaFuncAttributeMaxDynamicSharedMemorySize,
                         SMEM_DYN);

    const int mem_total = BATCH * (128 + 256 + 512 + 1024 + 784);
    zero_kernel<<<1024, 256>>>(mem_base, mem_total);
    zero_sync_kernel<<<1, 256>>>();
    split_kernel<<<1024, 256>>>(W2, W3, W4, W5);
    // layer-1 current (constant over timesteps): M=2048, N=128, K=100
    gemm_l1<<<dim3(2, 16), 256>>>(x, W1, b1, cur1, 128, 100);

    snn_persistent<<<NWORKERS, 256, SMEM_DYN>>>(b2, b3, b4, b5, out);
}

// round 13
// speedup vs baseline: 1.9369x; 1.9369x over previous
#include <cuda_runtime.h>
#include <cuda_fp16.h>
#include <cstdint>
#include <math.h>

// ---------------------------------------------------------------------------
// SNN 5-layer LIF, 25 steps, batch 2048, dims 100->128->256->512->1024->784.
// KEY STRUCTURE: only the elementwise LIF recurrence is sequential in t.
// spk1(all t) follows from cur1 alone; then each layer is ONE time-batched
// GEMM with M = 25*2048 = 51200 followed by an elementwise LIF scan (mem
// carried in a register over the 25 steps). 4 huge GEMMs + 5 scans, no
// wavefront, no parity buffers, no global mem state.
// GEMM numerics (locked): HMMA fp16, 2-way split with scaled lo
// (hi=fp16(w), lo=fp16(4096*(w-hi)); residual ~w*2^-24), dual accumulation
// chains, per-32K chunked flush into fp32 master. Products exact ({0,1} A).
// ---------------------------------------------------------------------------

#define BETA_ 0.95f
#define LO_SCALE 4096.0f
#define LO_INV 2.44140625e-4f  // 2^-12, exact

namespace {
constexpr int BATCH = 2048;
constexpr int TSTEPS = 25;
constexpr int MTOT = TSTEPS * BATCH;  // 51200 GEMM rows
constexpr int WSZ2 = 256 * 128, WSZ3 = 512 * 256, WSZ4 = 1024 * 512;
constexpr int WSZ5 = 784 * 1024;   // real
constexpr int WSZ5P = 832 * 1024;  // padded N to multiple of 64
constexpr size_t WOFF2 = 0;
constexpr size_t WOFF3 = WOFF2 + 2ull * WSZ2;
constexpr size_t WOFF4 = WOFF3 + 2ull * WSZ3;
constexpr size_t WOFF5 = WOFF4 + 2ull * WSZ4;
constexpr size_t WTOT = WOFF5 + 2ull * WSZ5P;
constexpr int SUB_B = 8192 + 2 * 4096;   // 32-K sub-tile: A 8K + 2 B splits
constexpr int STAGE_B = 2 * SUB_B;       // 64-K superstage = 32KB
constexpr int SMEM_DYN = 2 * STAGE_B;    // ping-pong ring = 64KB
}  // namespace

// ---- persistent scratch (__device__ globals; no allocs allowed) ----
__device__ __align__(16) float g_cur1[(size_t)BATCH * 128];
__device__ __align__(16) float g_cur2[(size_t)MTOT * 256];
__device__ __align__(16) float g_cur3[(size_t)MTOT * 512];
__device__ __align__(16) float g_cur4[(size_t)MTOT * 1024];
__device__ __align__(16) float g_cur5[(size_t)MTOT * 784];
__device__ __align__(16) __half g_spk1[(size_t)MTOT * 128];
__device__ __align__(16) __half g_spk2[(size_t)MTOT * 256];
__device__ __align__(16) __half g_spk3[(size_t)MTOT * 512];
__device__ __align__(16) __half g_spk4[(size_t)MTOT * 1024];
__device__ __align__(16) __half g_wsplit[WTOT];  // zero-init: L5 pad rows stay 0

// ======================= PTX helpers (arch-neutral) ========================
__device__ __forceinline__ uint32_t smem_u32(const void* p) {
    uint32_t a;
    asm("{ .reg .u64 t; cvta.to.shared.u64 t, %1; cvt.u32.u64 %0, t; }" : "=r"(a) : "l"(p));
    return a;
}
__device__ __forceinline__ void cp_async16(uint32_t dst, const void* src) {
    asm volatile("cp.async.cg.shared.global [%0], [%1], 16;" ::"r"(dst), "l"(src));
}
#define CP_COMMIT() asm volatile("cp.async.commit_group;" ::: "memory")
#define CP_WAIT0() asm volatile("cp.async.wait_group 0;" ::: "memory")

__device__ __forceinline__ void ldsm_x4(uint32_t& r0, uint32_t& r1, uint32_t& r2, uint32_t& r3,
                                        uint32_t addr) {
    asm volatile("ldmatrix.sync.aligned.m8n8.x4.shared.b16 {%0,%1,%2,%3}, [%4];"
                 : "=r"(r0), "=r"(r1), "=r"(r2), "=r"(r3)
                 : "r"(addr));
}
__device__ __forceinline__ void mma_f16(float* c, const uint32_t* a, const uint32_t* b) {
    asm volatile(
        "mma.sync.aligned.m16n8k16.row.col.f32.f16.f16.f32 "
        "{%0,%1,%2,%3}, {%4,%5,%6,%7}, {%8,%9}, {%0,%1,%2,%3};"
        : "+f"(c[0]), "+f"(c[1]), "+f"(c[2]), "+f"(c[3])
        : "r"(a[0]), "r"(a[1]), "r"(a[2]), "r"(a[3]), "r"(b[0]), "r"(b[1]));
}
__device__ __forceinline__ void mma_f16_z(float* d, const uint32_t* a, const uint32_t* b,
                                          const float* z) {
    asm volatile(
        "mma.sync.aligned.m16n8k16.row.col.f32.f16.f16.f32 "
        "{%0,%1,%2,%3}, {%4,%5,%6,%7}, {%8,%9}, {%10,%11,%12,%13};"
        : "=f"(d[0]), "=f"(d[1]), "=f"(d[2]), "=f"(d[3])
        : "r"(a[0]), "r"(a[1]), "r"(a[2]), "r"(a[3]), "r"(b[0]), "r"(b[1]),
          "f"(z[0]), "f"(z[1]), "f"(z[2]), "f"(z[3]));
}

// ======================= setup kernels =====================================
// 2-way fp16 split, lo scaled by 2^12 into the normal fp16 range
__global__ void split_kernel(const float* __restrict__ W2, const float* __restrict__ W3,
                             const float* __restrict__ W4, const float* __restrict__ W5) {
    const int total = WSZ2 + WSZ3 + WSZ4 + WSZ5;
    for (int i = blockIdx.x * blockDim.x + threadIdx.x; i < total;
         i += gridDim.x * blockDim.x) {
        const float* src;
        size_t base;
        int local, stride;
        if (i < WSZ2) { src = W2; base = WOFF2; local = i; stride = WSZ2; }
        else if (i < WSZ2 + WSZ3) { src = W3; base = WOFF3; local = i - WSZ2; stride = WSZ3; }
        else if (i < WSZ2 + WSZ3 + WSZ4) { src = W4; base = WOFF4; local = i - WSZ2 - WSZ3; stride = WSZ4; }
        else { src = W5; base = WOFF5; local = i - WSZ2 - WSZ3 - WSZ4; stride = WSZ5P; }
        float w = src[local];
        __half hi = __float2half_rn(w);
        float r1 = w - __half2float(hi);
        __half lo = __float2half_rn(r1 * LO_SCALE);
        g_wsplit[base + local] = hi;
        g_wsplit[base + (size_t)stride + local] = lo;
    }
}

// ---- fp32 SIMT GEMM for layer 1 (runs once): cur1 = relu(x@W1^T + b1) ----
namespace {
constexpr int L1BM = 128, L1BN = 64, L1BK = 16;
constexpr int LDA_S = L1BM + 4, LDB_S = L1BN + 4;
}
__global__ __launch_bounds__(256, 2) void gemm_l1(const float* __restrict__ A,
                                                  const float* __restrict__ W,
                                                  const float* __restrict__ bias,
                                                  float* __restrict__ outc, int N, int K) {
    __shared__ float As[L1BK * LDA_S];
    __shared__ float Bs[L1BK * LDB_S];
    const int tid = threadIdx.x;
    const int tx = tid & 15, ty = tid >> 4;
    const int bn0 = blockIdx.x * L1BN, bm0 = blockIdx.y * L1BM;
    float acc[8][4];
#pragma unroll
    for (int i = 0; i < 8; i++)
#pragma unroll
        for (int j = 0; j < 4; j++) acc[i][j] = 0.0f;
    const int ktiles = (K + L1BK - 1) / L1BK;
    for (int kt = 0; kt < ktiles; kt++) {
        const int k0 = kt * L1BK;
#pragma unroll
        for (int r = 0; r < 2; r++) {
            int f = tid + r * 256;
            int m = f >> 2, kq = f & 3, k = k0 + kq * 4;
            float4 v = make_float4(0.f, 0.f, 0.f, 0.f);
            if (k < K) v = *reinterpret_cast<const float4*>(A + (size_t)(bm0 + m) * K + k);
            As[(kq * 4 + 0) * LDA_S + m] = v.x;
            As[(kq * 4 + 1) * LDA_S + m] = v.y;
            As[(kq * 4 + 2) * LDA_S + m] = v.z;
            As[(kq * 4 + 3) * LDA_S + m] = v.w;
        }
        {
            int n = tid >> 2, kq = tid & 3, k = k0 + kq * 4, gn = bn0 + n;
            float4 v = make_float4(0.f, 0.f, 0.f, 0.f);
            if (k < K && gn < N) v = *reinterpret_cast<const float4*>(W + (size_t)gn * K + k);
            Bs[(kq * 4 + 0) * LDB_S + n] = v.x;
            Bs[(kq * 4 + 1) * LDB_S + n] = v.y;
            Bs[(kq * 4 + 2) * LDB_S + n] = v.z;
            Bs[(kq * 4 + 3) * LDB_S + n] = v.w;
        }
        __syncthreads();
#pragma unroll
        for (int k = 0; k < L1BK; k++) {
            float a[8], bb[4];
            *reinterpret_cast<float4*>(a) = *reinterpret_cast<const float4*>(&As[k * LDA_S + ty * 8]);
            *reinterpret_cast<float4*>(a + 4) =
                *reinterpret_cast<const float4*>(&As[k * LDA_S + ty * 8 + 4]);
            *reinterpret_cast<float4*>(bb) = *reinterpret_cast<const float4*>(&Bs[k * LDB_S + tx * 4]);
#pragma unroll
            for (int i = 0; i < 8; i++)
#pragma unroll
                for (int j = 0; j < 4; j++) acc[i][j] = fmaf(a[i], bb[j], acc[i][j]);
        }
        __syncthreads();
    }
#pragma unroll
    for (int j = 0; j < 4; j++) {
        int gn = bn0 + tx * 4 + j;
        if (gn >= N) continue;
        float bv = bias[gn];
#pragma unroll
        for (int i = 0; i < 8; i++) {
            int gm = bm0 + ty * 8 + i;
            outc[(size_t)gm * N + gn] = fmaxf(acc[i][j] + bv, 0.0f);
        }
    }
}

// =================== time-batched HMMA GEMM (M = 51200) ====================
// CTA tile 128x64; BK=64 superstage (two 32-K sub-tiles); ping-pong ring.
// Dual chains; flush accm += tmpH; accm = fma(2^-12, tmpL, .) per 32-K.
// Epilogue: cur = relu(acc + bias) stored fp32.
template <int N_REAL, int N_PAD, int K>
__global__ __launch_bounds__(256, 2) void gemm_cur(
    const __half* __restrict__ A, const __half* __restrict__ Wsp,
    const float* __restrict__ bias, float* __restrict__ cur) {
    extern __shared__ __align__(128) char smem[];
    constexpr int KT = K / 64;
    constexpr int A_BYTES = 8192, B_BYTES = 4096;

    const int tid = threadIdx.x;
    const int wid = tid >> 5, lane = tid & 31;
    const int wM = wid >> 2, wN = wid & 3;
    const int bn0 = blockIdx.x * 64;
    const int bm0 = blockIdx.y * 128;
    const size_t WSZ = (size_t)N_PAD * K;
    const uint32_t sb = smem_u32(smem);

    const float zf[4] = {0.0f, 0.0f, 0.0f, 0.0f};

    auto issue = [&](int kt) {
        const uint32_t st = sb + (kt & 1) * STAGE_B;
#pragma unroll
        for (int sub = 0; sub < 2; sub++) {
            const int k0 = kt * 64 + sub * 32;
            const uint32_t sd = st + sub * SUB_B;
#pragma unroll
            for (int i = 0; i < 2; i++) {
                int f = tid + i * 256;
                int row = f >> 2, c = f & 3;
                cp_async16(sd + row * 64 + ((c ^ ((row >> 1) & 3)) * 16),
                           A + (size_t)(bm0 + row) * K + k0 + c * 8);
            }
#pragma unroll
            for (int s = 0; s < 2; s++) {
                int row = tid >> 2, c = tid & 3;
                cp_async16(sd + A_BYTES + s * B_BYTES + row * 64 +
                               ((c ^ ((row >> 1) & 3)) * 16),
                           Wsp + (size_t)s * WSZ + (size_t)(bn0 + row) * K + k0 + c * 8);
            }
        }
    };

    float accm[4][2][4];
#pragma unroll
    for (int i = 0; i < 4; i++)
#pragma unroll
        for (int j = 0; j < 2; j++)
#pragma unroll
            for (int q = 0; q < 4; q++) accm[i][j][q] = 0.0f;

    issue(0);
    CP_COMMIT();
    for (int kt = 0; kt < KT; kt++) {
        CP_WAIT0();
        __syncthreads();
        if (kt + 1 < KT) issue(kt + 1);
        CP_COMMIT();
#pragma unroll
        for (int sub = 0; sub < 2; sub++) {
            const uint32_t sA = sb + (kt & 1) * STAGE_B + sub * SUB_B;
            const uint32_t sB = sA + A_BYTES;

            float tmpH[4][2][4], tmpL[4][2][4];
#pragma unroll
            for (int k16 = 0; k16 < 2; k16++) {
                uint32_t afr[4][4];
#pragma unroll
                for (int mf = 0; mf < 4; mf++) {
                    int row = wM * 64 + mf * 16 + (lane & 15);
                    int chunk = k16 * 2 + ((lane >> 4) & 1);
                    uint32_t addr = sA + row * 64 + ((chunk ^ ((row >> 1) & 3)) * 16);
                    ldsm_x4(afr[mf][0], afr[mf][1], afr[mf][2], afr[mf][3], addr);
                }
#pragma unroll
                for (int s = 0; s < 2; s++) {
                    uint32_t bfr[4];
                    {
                        int row = wN * 16 + (lane & 7) + ((lane >> 4) & 1) * 8;
                        int chunk = k16 * 2 + ((lane >> 3) & 1);
                        uint32_t addr =
                            sB + s * B_BYTES + row * 64 + ((chunk ^ ((row >> 1) & 3)) * 16);
                        ldsm_x4(bfr[0], bfr[1], bfr[2], bfr[3], addr);
                    }
                    float (*tmp)[2][4] = (s == 0) ? tmpH : tmpL;
#pragma unroll
                    for (int mf = 0; mf < 4; mf++) {
                        if (k16 == 0) {
                            mma_f16_z(tmp[mf][0], afr[mf], bfr, zf);
                            mma_f16_z(tmp[mf][1], afr[mf], bfr + 2, zf);
                        } else {
                            mma_f16(tmp[mf][0], afr[mf], bfr);
                            mma_f16(tmp[mf][1], afr[mf], bfr + 2);
                        }
                    }
                }
            }
#pragma unroll
            for (int i = 0; i < 4; i++)
#pragma unroll
                for (int j = 0; j < 2; j++)
#pragma unroll
                    for (int q = 0; q < 4; q++) {
                        float a = accm[i][j][q] + tmpH[i][j][q];
                        accm[i][j][q] = fmaf(LO_INV, tmpL[i][j][q], a);
                    }
        }
    }

    // ---- epilogue: cur = relu(acc + bias), fp32 ----
    const int tg = lane >> 2;
    const int tc = (lane & 3) * 2;
#pragma unroll
    for (int mf = 0; mf < 4; mf++) {
#pragma unroll
        for (int nf = 0; nf < 2; nf++) {
            int gn0 = bn0 + wN * 16 + nf * 8 + tc;
            int r0 = bm0 + wM * 64 + mf * 16 + tg;
#pragma unroll
            for (int h = 0; h < 2; h++) {
                int r = r0 + h * 8;
#pragma unroll
                for (int q = 0; q < 2; q++) {
                    int n = gn0 + q;
                    if (N_REAL == N_PAD || n < N_REAL) {
                        float v = accm[mf][nf][h * 2 + q];
                        cur[(size_t)r * N_REAL + n] = fmaxf(v + bias[n], 0.0f);
                    }
                }
            }
        }
    }
}

// ======================= LIF scan kernels ==================================
// lif1: cur constant over t. Each thread owns one (b,n); mem in register.
__global__ void lif1_scan(const float* __restrict__ cur, __half* __restrict__ spk) {
    constexpr int ELEMS = BATCH * 128;
    for (int i = blockIdx.x * blockDim.x + threadIdx.x; i < ELEMS;
         i += gridDim.x * blockDim.x) {
        const float c = cur[i];
        float mem = 0.0f;
#pragma unroll
        for (int t = 0; t < TSTEPS; t++) {
            float reset = (mem > 1.0f) ? 1.0f : 0.0f;
            mem = fmaf(BETA_, mem, c) - reset;
            spk[(size_t)t * ELEMS + i] = __float2half_rn((mem > 1.0f) ? 1.0f : 0.0f);
        }
    }
}

// mid layers: cur[t][b][n] -> spk[t][b][n] (fp16)
template <int N>
__global__ void lif_scan(const float* __restrict__ cur, __half* __restrict__ spk) {
    constexpr int ELEMS = BATCH * N;
    for (int i = blockIdx.x * blockDim.x + threadIdx.x; i < ELEMS;
         i += gridDim.x * blockDim.x) {
        float mem = 0.0f;
#pragma unroll
        for (int t = 0; t < TSTEPS; t++) {
            float c = cur[(size_t)t * ELEMS + i];
            float reset = (mem > 1.0f) ? 1.0f : 0.0f;
            mem = fmaf(BETA_, mem, c) - reset;
            spk[(size_t)t * ELEMS + i] = __float2half_rn((mem > 1.0f) ? 1.0f : 0.0f);
        }
    }
}

// last layer: writes spikes (fp32) + tanh(mem) to d_out
__global__ void lif5_scan(const float* __restrict__ cur, float* __restrict__ out) {
    constexpr int ELEMS = BATCH * 784;
    const size_t OUT_HALF = (size_t)TSTEPS * ELEMS;
    for (int i = blockIdx.x * blockDim.x + threadIdx.x; i < ELEMS;
         i += gridDim.x * blockDim.x) {
        float mem = 0.0f;
#pragma unroll
        for (int t = 0; t < TSTEPS; t++) {
            float c = cur[(size_t)t * ELEMS + i];
            float reset = (mem > 1.0f) ? 1.0f : 0.0f;
            mem = fmaf(BETA_, mem, c) - reset;
            out[(size_t)t * ELEMS + i] = (mem > 1.0f) ? 1.0f : 0.0f;
            out[OUT_HALF + (size_t)t * ELEMS + i] = tanhf(mem);
        }
    }
}

// ============================= launch ======================================
extern "C" void kernel_launch(void* const* d_in, const int* in_sizes, int n_in,
                              void* d_out, int out_size) {
    const float* x = (const float*)d_in[0];
    const float* W1 = (const float*)d_in[1];
    const float* b1 = (const float*)d_in[2];
    const float* W2 = (const float*)d_in[3];
    const float* b2 = (const float*)d_in[4];
    const float* W3 = (const float*)d_in[5];
    const float* b3 = (const float*)d_in[6];
    const float* W4 = (const float*)d_in[7];
    const float* b4 = (const float*)d_in[8];
    const float* W5 = (const float*)d_in[9];
    const float* b5 = (const float*)d_in[10];
    float* out = (float*)d_out;

    float *cur1, *cur2, *cur3, *cur4, *cur5;
    __half *spk1, *spk2, *spk3, *spk4, *wsp;
    cudaGetSymbolAddress((void**)&cur1, g_cur1);
    cudaGetSymbolAddress((void**)&cur2, g_cur2);
    cudaGetSymbolAddress((void**)&cur3, g_cur3);
    cudaGetSymbolAddress((void**)&cur4, g_cur4);
    cudaGetSymbolAddress((void**)&cur5, g_cur5);
    cudaGetSymbolAddress((void**)&spk1, g_spk1);
    cudaGetSymbolAddress((void**)&spk2, g_spk2);
    cudaGetSymbolAddress((void**)&spk3, g_spk3);
    cudaGetSymbolAddress((void**)&spk4, g_spk4);
    cudaGetSymbolAddress((void**)&wsp, g_wsplit);

    cudaFuncSetAttribute(gemm_cur<256, 256, 128>,
                         cudaFuncAttributeMaxDynamicSharedMemorySize, SMEM_DYN);
    cudaFuncSetAttribute(gemm_cur<512, 512, 256>,
                         cudaFuncAttributeMaxDynamicSharedMemorySize, SMEM_DYN);
    cudaFuncSetAttribute(gemm_cur<1024, 1024, 512>,
                         cudaFuncAttributeMaxDynamicSharedMemorySize, SMEM_DYN);
    cudaFuncSetAttribute(gemm_cur<784, 832, 1024>,
                         cudaFuncAttributeMaxDynamicSharedMemorySize, SMEM_DYN);

    constexpr int MT = MTOT / 128;  // 400 m-tiles

    split_kernel<<<1024, 256>>>(W2, W3, W4, W5);
    // layer-1 current (constant over timesteps): M=2048, N=128, K=100
    gemm_l1<<<dim3(2, 16), 256>>>(x, W1, b1, cur1, 128, 100);
    lif1_scan<<<512, 256>>>(cur1, spk1);

    gemm_cur<256, 256, 128><<<dim3(4, MT), 256, SMEM_DYN>>>(spk1, wsp + WOFF2, b2, cur2);
    lif_scan<256><<<1024, 256>>>(cur2, spk2);

    gemm_cur<512, 512, 256><<<dim3(8, MT), 256, SMEM_DYN>>>(spk2, wsp + WOFF3, b3, cur3);
    lif_scan<512><<<2048, 256>>>(cur3, spk3);

    gemm_cur<1024, 1024, 512><<<dim3(16, MT), 256, SMEM_DYN>>>(spk3, wsp + WOFF4, b4, cur4);
    lif_scan<1024><<<4096, 256>>>(cur4, spk4);

    gemm_cur<784, 832, 1024><<<dim3(13, MT), 256, SMEM_DYN>>>(spk4, wsp + WOFF5, b5, cur5);
    lif5_scan<<<3136, 256>>>(cur5, out);
}

// round 14
// speedup vs baseline: 1.9889x; 1.0269x over previous
#include <cuda_runtime.h>
#include <cuda_fp16.h>
#include <cstdint>
#include <math.h>

// ---------------------------------------------------------------------------
// SNN 5-layer LIF, 25 steps, batch 2048, dims 100->128->256->512->1024->784.
// Time-batched layer pipeline: only the elementwise LIF recurrence is
// sequential in t, so each layer is ONE GEMM with M = 25*2048 = 51200
// followed by an elementwise LIF scan (mem in a register over t).
// GEMM numerics: HMMA fp16, 2-way split with scaled lo (hi=fp16(w),
// lo=fp16(4096*(w-hi)); residual ~w*2^-24). Accumulation restructured to
// minimize issue-slot overhead:
//   - hi: per-64K-superstage temp chain, flushed into fp32 master (RN FADD)
//   - lo: ONE tensor-core chain across all K (products ~0.1 scaled; final
//     truncation ~3e-9 absolute), folded in once at the end via FMA.
// Products exact (A is {0,1} spikes).
// ---------------------------------------------------------------------------

#define BETA_ 0.95f
#define LO_SCALE 4096.0f
#define LO_INV 2.44140625e-4f  // 2^-12, exact

namespace {
constexpr int BATCH = 2048;
constexpr int TSTEPS = 25;
constexpr int MTOT = TSTEPS * BATCH;  // 51200 GEMM rows
constexpr int WSZ2 = 256 * 128, WSZ3 = 512 * 256, WSZ4 = 1024 * 512;
constexpr int WSZ5 = 784 * 1024;   // real
constexpr int WSZ5P = 832 * 1024;  // padded N to multiple of 64
constexpr size_t WOFF2 = 0;
constexpr size_t WOFF3 = WOFF2 + 2ull * WSZ2;
constexpr size_t WOFF4 = WOFF3 + 2ull * WSZ3;
constexpr size_t WOFF5 = WOFF4 + 2ull * WSZ4;
constexpr size_t WTOT = WOFF5 + 2ull * WSZ5P;
constexpr int SUB_B = 8192 + 2 * 4096;   // 32-K sub-tile: A 8K + 2 B splits
constexpr int STAGE_B = 2 * SUB_B;       // 64-K superstage = 32KB
constexpr int SMEM_DYN = 2 * STAGE_B;    // ping-pong ring = 64KB
}  // namespace

// ---- persistent scratch (__device__ globals; no allocs allowed) ----
__device__ __align__(16) float g_cur1[(size_t)BATCH * 128];
__device__ __align__(16) float g_cur2[(size_t)MTOT * 256];
__device__ __align__(16) float g_cur3[(size_t)MTOT * 512];
__device__ __align__(16) float g_cur4[(size_t)MTOT * 1024];
__device__ __align__(16) float g_cur5[(size_t)MTOT * 784];
__device__ __align__(16) __half g_spk1[(size_t)MTOT * 128];
__device__ __align__(16) __half g_spk2[(size_t)MTOT * 256];
__device__ __align__(16) __half g_spk3[(size_t)MTOT * 512];
__device__ __align__(16) __half g_spk4[(size_t)MTOT * 1024];
__device__ __align__(16) __half g_wsplit[WTOT];  // zero-init: L5 pad rows stay 0

// ======================= PTX helpers (arch-neutral) ========================
__device__ __forceinline__ uint32_t smem_u32(const void* p) {
    uint32_t a;
    asm("{ .reg .u64 t; cvta.to.shared.u64 t, %1; cvt.u32.u64 %0, t; }" : "=r"(a) : "l"(p));
    return a;
}
__device__ __forceinline__ void cp_async16(uint32_t dst, const void* src) {
    asm volatile("cp.async.cg.shared.global [%0], [%1], 16;" ::"r"(dst), "l"(src));
}
#define CP_COMMIT() asm volatile("cp.async.commit_group;" ::: "memory")
#define CP_WAIT0() asm volatile("cp.async.wait_group 0;" ::: "memory")

__device__ __forceinline__ void ldsm_x4(uint32_t& r0, uint32_t& r1, uint32_t& r2, uint32_t& r3,
                                        uint32_t addr) {
    asm volatile("ldmatrix.sync.aligned.m8n8.x4.shared.b16 {%0,%1,%2,%3}, [%4];"
                 : "=r"(r0), "=r"(r1), "=r"(r2), "=r"(r3)
                 : "r"(addr));
}
__device__ __forceinline__ void mma_f16(float* c, const uint32_t* a, const uint32_t* b) {
    asm volatile(
        "mma.sync.aligned.m16n8k16.row.col.f32.f16.f16.f32 "
        "{%0,%1,%2,%3}, {%4,%5,%6,%7}, {%8,%9}, {%0,%1,%2,%3};"
        : "+f"(c[0]), "+f"(c[1]), "+f"(c[2]), "+f"(c[3])
        : "r"(a[0]), "r"(a[1]), "r"(a[2]), "r"(a[3]), "r"(b[0]), "r"(b[1]));
}
__device__ __forceinline__ void mma_f16_z(float* d, const uint32_t* a, const uint32_t* b,
                                          const float* z) {
    asm volatile(
        "mma.sync.aligned.m16n8k16.row.col.f32.f16.f16.f32 "
        "{%0,%1,%2,%3}, {%4,%5,%6,%7}, {%8,%9}, {%10,%11,%12,%13};"
        : "=f"(d[0]), "=f"(d[1]), "=f"(d[2]), "=f"(d[3])
        : "r"(a[0]), "r"(a[1]), "r"(a[2]), "r"(a[3]), "r"(b[0]), "r"(b[1]),
          "f"(z[0]), "f"(z[1]), "f"(z[2]), "f"(z[3]));
}

// ======================= setup kernels =====================================
// 2-way fp16 split, lo scaled by 2^12 into the normal fp16 range
__global__ void split_kernel(const float* __restrict__ W2, const float* __restrict__ W3,
                             const float* __restrict__ W4, const float* __restrict__ W5) {
    const int total = WSZ2 + WSZ3 + WSZ4 + WSZ5;
    for (int i = blockIdx.x * blockDim.x + threadIdx.x; i < total;
         i += gridDim.x * blockDim.x) {
        const float* src;
        size_t base;
        int local, stride;
        if (i < WSZ2) { src = W2; base = WOFF2; local = i; stride = WSZ2; }
        else if (i < WSZ2 + WSZ3) { src = W3; base = WOFF3; local = i - WSZ2; stride = WSZ3; }
        else if (i < WSZ2 + WSZ3 + WSZ4) { src = W4; base = WOFF4; local = i - WSZ2 - WSZ3; stride = WSZ4; }
        else { src = W5; base = WOFF5; local = i - WSZ2 - WSZ3 - WSZ4; stride = WSZ5P; }
        float w = src[local];
        __half hi = __float2half_rn(w);
        float r1 = w - __half2float(hi);
        __half lo = __float2half_rn(r1 * LO_SCALE);
        g_wsplit[base + local] = hi;
        g_wsplit[base + (size_t)stride + local] = lo;
    }
}

// ---- fp32 SIMT GEMM for layer 1 (runs once): cur1 = relu(x@W1^T + b1) ----
namespace {
constexpr int L1BM = 128, L1BN = 64, L1BK = 16;
constexpr int LDA_S = L1BM + 4, LDB_S = L1BN + 4;
}
__global__ __launch_bounds__(256, 2) void gemm_l1(const float* __restrict__ A,
                                                  const float* __restrict__ W,
                                                  const float* __restrict__ bias,
                                                  float* __restrict__ outc, int N, int K) {
    __shared__ float As[L1BK * LDA_S];
    __shared__ float Bs[L1BK * LDB_S];
    const int tid = threadIdx.x;
    const int tx = tid & 15, ty = tid >> 4;
    const int bn0 = blockIdx.x * L1BN, bm0 = blockIdx.y * L1BM;
    float acc[8][4];
#pragma unroll
    for (int i = 0; i < 8; i++)
#pragma unroll
        for (int j = 0; j < 4; j++) acc[i][j] = 0.0f;
    const int ktiles = (K + L1BK - 1) / L1BK;
    for (int kt = 0; kt < ktiles; kt++) {
        const int k0 = kt * L1BK;
#pragma unroll
        for (int r = 0; r < 2; r++) {
            int f = tid + r * 256;
            int m = f >> 2, kq = f & 3, k = k0 + kq * 4;
            float4 v = make_float4(0.f, 0.f, 0.f, 0.f);
            if (k < K) v = *reinterpret_cast<const float4*>(A + (size_t)(bm0 + m) * K + k);
            As[(kq * 4 + 0) * LDA_S + m] = v.x;
            As[(kq * 4 + 1) * LDA_S + m] = v.y;
            As[(kq * 4 + 2) * LDA_S + m] = v.z;
            As[(kq * 4 + 3) * LDA_S + m] = v.w;
        }
        {
            int n = tid >> 2, kq = tid & 3, k = k0 + kq * 4, gn = bn0 + n;
            float4 v = make_float4(0.f, 0.f, 0.f, 0.f);
            if (k < K && gn < N) v = *reinterpret_cast<const float4*>(W + (size_t)gn * K + k);
            Bs[(kq * 4 + 0) * LDB_S + n] = v.x;
            Bs[(kq * 4 + 1) * LDB_S + n] = v.y;
            Bs[(kq * 4 + 2) * LDB_S + n] = v.z;
            Bs[(kq * 4 + 3) * LDB_S + n] = v.w;
        }
        __syncthreads();
#pragma unroll
        for (int k = 0; k < L1BK; k++) {
            float a[8], bb[4];
            *reinterpret_cast<float4*>(a) = *reinterpret_cast<const float4*>(&As[k * LDA_S + ty * 8]);
            *reinterpret_cast<float4*>(a + 4) =
                *reinterpret_cast<const float4*>(&As[k * LDA_S + ty * 8 + 4]);
            *reinterpret_cast<float4*>(bb) = *reinterpret_cast<const float4*>(&Bs[k * LDB_S + tx * 4]);
#pragma unroll
            for (int i = 0; i < 8; i++)
#pragma unroll
                for (int j = 0; j < 4; j++) acc[i][j] = fmaf(a[i], bb[j], acc[i][j]);
        }
        __syncthreads();
    }
#pragma unroll
    for (int j = 0; j < 4; j++) {
        int gn = bn0 + tx * 4 + j;
        if (gn >= N) continue;
        float bv = bias[gn];
#pragma unroll
        for (int i = 0; i < 8; i++) {
            int gm = bm0 + ty * 8 + i;
            outc[(size_t)gm * N + gn] = fmaxf(acc[i][j] + bv, 0.0f);
        }
    }
}

// =================== time-batched HMMA GEMM (M = 51200) ====================
// CTA tile 128x64; BK=64 superstage; ping-pong ring. hi: per-superstage temp
// chain flushed into fp32 master. lo: single tensor-core chain over all K,
// folded once at the end (accm = fma(2^-12, accL, accm)).
template <int N_REAL, int N_PAD, int K>
__global__ __launch_bounds__(256, 2) void gemm_cur(
    const __half* __restrict__ A, const __half* __restrict__ Wsp,
    const float* __restrict__ bias, float* __restrict__ cur) {
    extern __shared__ __align__(128) char smem[];
    constexpr int KT = K / 64;
    constexpr int A_BYTES = 8192, B_BYTES = 4096;

    const int tid = threadIdx.x;
    const int wid = tid >> 5, lane = tid & 31;
    const int wM = wid >> 2, wN = wid & 3;
    const int bn0 = blockIdx.x * 64;
    const int bm0 = blockIdx.y * 128;
    const size_t WSZ = (size_t)N_PAD * K;
    const uint32_t sb = smem_u32(smem);

    const float zf[4] = {0.0f, 0.0f, 0.0f, 0.0f};

    auto issue = [&](int kt) {
        const uint32_t st = sb + (kt & 1) * STAGE_B;
#pragma unroll
        for (int sub = 0; sub < 2; sub++) {
            const int k0 = kt * 64 + sub * 32;
            const uint32_t sd = st + sub * SUB_B;
#pragma unroll
            for (int i = 0; i < 2; i++) {
                int f = tid + i * 256;
                int row = f >> 2, c = f & 3;
                cp_async16(sd + row * 64 + ((c ^ ((row >> 1) & 3)) * 16),
                           A + (size_t)(bm0 + row) * K + k0 + c * 8);
            }
#pragma unroll
            for (int s = 0; s < 2; s++) {
                int row = tid >> 2, c = tid & 3;
                cp_async16(sd + A_BYTES + s * B_BYTES + row * 64 +
                               ((c ^ ((row >> 1) & 3)) * 16),
                           Wsp + (size_t)s * WSZ + (size_t)(bn0 + row) * K + k0 + c * 8);
            }
        }
    };

    float accm[4][2][4];  // hi master (RN fp32)
    float accL[4][2][4];  // lo tensor-core chain (scaled space)
#pragma unroll
    for (int i = 0; i < 4; i++)
#pragma unroll
        for (int j = 0; j < 2; j++)
#pragma unroll
            for (int q = 0; q < 4; q++) accm[i][j][q] = 0.0f;

    issue(0);
    CP_COMMIT();
    for (int kt = 0; kt < KT; kt++) {
        CP_WAIT0();
        __syncthreads();
        if (kt + 1 < KT) issue(kt + 1);
        CP_COMMIT();

        float tmpH[4][2][4];  // hi chain for this 64-K superstage
#pragma unroll
        for (int sub = 0; sub < 2; sub++) {
            const uint32_t sA = sb + (kt & 1) * STAGE_B + sub * SUB_B;
            const uint32_t sB = sA + A_BYTES;
#pragma unroll
            for (int k16 = 0; k16 < 2; k16++) {
                const bool firstH = (sub == 0 && k16 == 0);
                const bool firstL = (kt == 0 && firstH);
                uint32_t afr[4][4];
#pragma unroll
                for (int mf = 0; mf < 4; mf++) {
                    int row = wM * 64 + mf * 16 + (lane & 15);
                    int chunk = k16 * 2 + ((lane >> 4) & 1);
                    uint32_t addr = sA + row * 64 + ((chunk ^ ((row >> 1) & 3)) * 16);
                    ldsm_x4(afr[mf][0], afr[mf][1], afr[mf][2], afr[mf][3], addr);
                }
                // hi split -> tmpH chain
                {
                    uint32_t bfr[4];
                    int row = wN * 16 + (lane & 7) + ((lane >> 4) & 1) * 8;
                    int chunk = k16 * 2 + ((lane >> 3) & 1);
                    uint32_t addr = sB + row * 64 + ((chunk ^ ((row >> 1) & 3)) * 16);
                    ldsm_x4(bfr[0], bfr[1], bfr[2], bfr[3], addr);
#pragma unroll
                    for (int mf = 0; mf < 4; mf++) {
                        if (firstH) {
                            mma_f16_z(tmpH[mf][0], afr[mf], bfr, zf);
                            mma_f16_z(tmpH[mf][1], afr[mf], bfr + 2, zf);
                        } else {
                            mma_f16(tmpH[mf][0], afr[mf], bfr);
                            mma_f16(tmpH[mf][1], afr[mf], bfr + 2);
                        }
                    }
                }
                // lo split -> accL chain (whole K)
                {
                    uint32_t bfr[4];
                    int row = wN * 16 + (lane & 7) + ((lane >> 4) & 1) * 8;
                    int chunk = k16 * 2 + ((lane >> 3) & 1);
                    uint32_t addr =
                        sB + B_BYTES + row * 64 + ((chunk ^ ((row >> 1) & 3)) * 16);
                    ldsm_x4(bfr[0], bfr[1], bfr[2], bfr[3], addr);
#pragma unroll
                    for (int mf = 0; mf < 4; mf++) {
                        if (firstL) {
                            mma_f16_z(accL[mf][0], afr[mf], bfr, zf);
                            mma_f16_z(accL[mf][1], afr[mf], bfr + 2, zf);
                        } else {
                            mma_f16(accL[mf][0], afr[mf], bfr);
                            mma_f16(accL[mf][1], afr[mf], bfr + 2);
                        }
                    }
                }
            }
        }
        // flush hi superstage into master (RN fp32 adds)
#pragma unroll
        for (int i = 0; i < 4; i++)
#pragma unroll
            for (int j = 0; j < 2; j++)
#pragma unroll
                for (int q = 0; q < 4; q++) accm[i][j][q] += tmpH[i][j][q];
    }
    // fold lo chain once: accm += 2^-12 * accL
#pragma unroll
    for (int i = 0; i < 4; i++)
#pragma unroll
        for (int j = 0; j < 2; j++)
#pragma unroll
            for (int q = 0; q < 4; q++)
                accm[i][j][q] = fmaf(LO_INV, accL[i][j][q], accm[i][j][q]);

    // ---- epilogue: cur = relu(acc + bias), fp32 ----
    const int tg = lane >> 2;
    const int tc = (lane & 3) * 2;
#pragma unroll
    for (int mf = 0; mf < 4; mf++) {
#pragma unroll
        for (int nf = 0; nf < 2; nf++) {
            int gn0 = bn0 + wN * 16 + nf * 8 + tc;
            int r0 = bm0 + wM * 64 + mf * 16 + tg;
#pragma unroll
            for (int h = 0; h < 2; h++) {
                int r = r0 + h * 8;
#pragma unroll
                for (int q = 0; q < 2; q++) {
                    int n = gn0 + q;
                    if (N_REAL == N_PAD || n < N_REAL) {
                        float v = accm[mf][nf][h * 2 + q];
                        cur[(size_t)r * N_REAL + n] = fmaxf(v + bias[n], 0.0f);
                    }
                }
            }
        }
    }
}

// ======================= LIF scan kernels ==================================
__global__ void lif1_scan(const float* __restrict__ cur, __half* __restrict__ spk) {
    constexpr int ELEMS = BATCH * 128;
    for (int i = blockIdx.x * blockDim.x + threadIdx.x; i < ELEMS;
         i += gridDim.x * blockDim.x) {
        const float c = cur[i];
        float mem = 0.0f;
#pragma unroll
        for (int t = 0; t < TSTEPS; t++) {
            float reset = (mem > 1.0f) ? 1.0f : 0.0f;
            mem = fmaf(BETA_, mem, c) - reset;
            spk[(size_t)t * ELEMS + i] = __float2half_rn((mem > 1.0f) ? 1.0f : 0.0f);
        }
    }
}

template <int N>
__global__ void lif_scan(const float* __restrict__ cur, __half* __restrict__ spk) {
    constexpr int ELEMS = BATCH * N;
    for (int i = blockIdx.x * blockDim.x + threadIdx.x; i < ELEMS;
         i += gridDim.x * blockDim.x) {
        float mem = 0.0f;
#pragma unroll
        for (int t = 0; t < TSTEPS; t++) {
            float c = cur[(size_t)t * ELEMS + i];
            float reset = (mem > 1.0f) ? 1.0f : 0.0f;
            mem = fmaf(BETA_, mem, c) - reset;
            spk[(size_t)t * ELEMS + i] = __float2half_rn((mem > 1.0f) ? 1.0f : 0.0f);
        }
    }
}

__global__ void lif5_scan(const float* __restrict__ cur, float* __restrict__ out) {
    constexpr int ELEMS = BATCH * 784;
    const size_t OUT_HALF = (size_t)TSTEPS * ELEMS;
    for (int i = blockIdx.x * blockDim.x + threadIdx.x; i < ELEMS;
         i += gridDim.x * blockDim.x) {
        float mem = 0.0f;
#pragma unroll
        for (int t = 0; t < TSTEPS; t++) {
            float c = cur[(size_t)t * ELEMS + i];
            float reset = (mem > 1.0f) ? 1.0f : 0.0f;
            mem = fmaf(BETA_, mem, c) - reset;
            out[(size_t)t * ELEMS + i] = (mem > 1.0f) ? 1.0f : 0.0f;
            out[OUT_HALF + (size_t)t * ELEMS + i] = tanhf(mem);
        }
    }
}

// ============================= launch ======================================
extern "C" void kernel_launch(void* const* d_in, const int* in_sizes, int n_in,
                              void* d_out, int out_size) {
    const float* x = (const float*)d_in[0];
    const float* W1 = (const float*)d_in[1];
    const float* b1 = (const float*)d_in[2];
    const float* W2 = (const float*)d_in[3];
    const float* b2 = (const float*)d_in[4];
    const float* W3 = (const float*)d_in[5];
    const float* b3 = (const float*)d_in[6];
    const float* W4 = (const float*)d_in[7];
    const float* b4 = (const float*)d_in[8];
    const float* W5 = (const float*)d_in[9];
    const float* b5 = (const float*)d_in[10];
    float* out = (float*)d_out;

    float *cur1, *cur2, *cur3, *cur4, *cur5;
    __half *spk1, *spk2, *spk3, *spk4, *wsp;
    cudaGetSymbolAddress((void**)&cur1, g_cur1);
    cudaGetSymbolAddress((void**)&cur2, g_cur2);
    cudaGetSymbolAddress((void**)&cur3, g_cur3);
    cudaGetSymbolAddress((void**)&cur4, g_cur4);
    cudaGetSymbolAddress((void**)&cur5, g_cur5);
    cudaGetSymbolAddress((void**)&spk1, g_spk1);
    cudaGetSymbolAddress((void**)&spk2, g_spk2);
    cudaGetSymbolAddress((void**)&spk3, g_spk3);
    cudaGetSymbolAddress((void**)&spk4, g_spk4);
    cudaGetSymbolAddress((void**)&wsp, g_wsplit);

    cudaFuncSetAttribute(gemm_cur<256, 256, 128>,
                         cudaFuncAttributeMaxDynamicSharedMemorySize, SMEM_DYN);
    cudaFuncSetAttribute(gemm_cur<512, 512, 256>,
                         cudaFuncAttributeMaxDynamicSharedMemorySize, SMEM_DYN);
    cudaFuncSetAttribute(gemm_cur<1024, 1024, 512>,
                         cudaFuncAttributeMaxDynamicSharedMemorySize, SMEM_DYN);
    cudaFuncSetAttribute(gemm_cur<784, 832, 1024>,
                         cudaFuncAttributeMaxDynamicSharedMemorySize, SMEM_DYN);

    constexpr int MT = MTOT / 128;  // 400 m-tiles

    split_kernel<<<1024, 256>>>(W2, W3, W4, W5);
    // layer-1 current (constant over timesteps): M=2048, N=128, K=100
    gemm_l1<<<dim3(2, 16), 256>>>(x, W1, b1, cur1, 128, 100);
    lif1_scan<<<512, 256>>>(cur1, spk1);

    gemm_cur<256, 256, 128><<<dim3(4, MT), 256, SMEM_DYN>>>(spk1, wsp + WOFF2, b2, cur2);
    lif_scan<256><<<1024, 256>>>(cur2, spk2);

    gemm_cur<512, 512, 256><<<dim3(8, MT), 256, SMEM_DYN>>>(spk2, wsp + WOFF3, b3, cur3);
    lif_scan<512><<<2048, 256>>>(cur3, spk3);

    gemm_cur<1024, 1024, 512><<<dim3(16, MT), 256, SMEM_DYN>>>(spk3, wsp + WOFF4, b4, cur4);
    lif_scan<1024><<<4096, 256>>>(cur4, spk4);

    gemm_cur<784, 832, 1024><<<dim3(13, MT), 256, SMEM_DYN>>>(spk4, wsp + WOFF5, b5, cur5);
    lif5_scan<<<3136, 256>>>(cur5, out);
}